// round 16
// baseline (speedup 1.0000x reference)
#include <cuda_runtime.h>
#include <cuda_fp16.h>
#include <stdint.h>
#include <math.h>

// Problem dims (fixed by reference setup_inputs)
#define BATCH 8
#define SQ    2048
#define SKV   2048
#define HID   1024

#define NX ((size_t)BATCH * SQ * HID)     // 16,777,216
#define NW ((size_t)HID * HID)            // 1,048,576
#define NS ((size_t)BATCH * SQ * SKV)    // 33,554,432

// ---------------------------------------------------------------------------
// Scratch (allocation-free rule: __device__ globals)
// ---------------------------------------------------------------------------
__device__ __half gXq1[NX];                // Xq fp16 single
__device__ __half gXk1[NX];                // Xk fp16 single
__device__ __half gWqth[NW], gWqtl[NW];    // Wq^T pair
__device__ __half gWkth[NW], gWktl[NW];    // Wk^T pair
__device__ __half gWvt[NW];                // Wv^T single
__device__ __half gQ1[NX];                 // Q single
__device__ __half gK1[NX];                 // K single
__device__ __half gVt[NX];                 // V^T single  [HID][BATCH*SKV]
__device__ float  gS[NS];                  // scores fp32
__device__ __half gSp[NS];                 // probs fp16 single

// ---------------------------------------------------------------------------
// helpers
// ---------------------------------------------------------------------------
__device__ __forceinline__ void split2h(float v, __half& h, __half& l) {
    h = __float2half_rn(v);
    l = __float2half_rn(v - __half2float(h));
}

__device__ __forceinline__ void cvt4h(__half* P, size_t idx, float4 v) {
    *reinterpret_cast<__half2*>(P + idx)     = __halves2half2(__float2half_rn(v.x), __float2half_rn(v.y));
    *reinterpret_cast<__half2*>(P + idx + 2) = __halves2half2(__float2half_rn(v.z), __float2half_rn(v.w));
}

// mma.sync m16n8k16 fp16 -> fp32 accumulate
__device__ __forceinline__ void mma_f16(float* d, const uint32_t* a, const uint32_t* b) {
    asm volatile(
        "mma.sync.aligned.m16n8k16.row.col.f32.f16.f16.f32 "
        "{%0,%1,%2,%3}, {%4,%5,%6,%7}, {%8,%9}, {%0,%1,%2,%3};"
        : "+f"(d[0]), "+f"(d[1]), "+f"(d[2]), "+f"(d[3])
        : "r"(a[0]), "r"(a[1]), "r"(a[2]), "r"(a[3]),
          "r"(b[0]), "r"(b[1]));
}

typedef uint32_t SmemT[2][3][2048];   // [stage][A,Bh,Bl][word]  48 KB

// ---------------------------------------------------------------------------
// GEMM body: C[M,N] = A * B^T (+epilogue). A fp16 single.
//   terms=2: B pair (a*bh + a*bl)   terms=1: B single (a*b)
// epi: 0 plain fp32 | 2 scores: v*scale + (1-mask[n])*(-1e4), fp32 out
//      3 +bias[m] -> fp16 single | 4 +bias[n] -> fp16 single
// Block 128x128, BK=32 (two 16-k sub-stages), 256 threads = 8 warps (2x4),
// warp tile 64x32. Fragment-packed smem, conflict-free STS.128 staging;
// one __syncthreads per 32-k chunk. (Validated R14 structure; terms/epi are
// call-site literals -> const-folded clones.)
// ---------------------------------------------------------------------------
__device__ __forceinline__ void gemm_body(
    const __half* __restrict__ Ah,
    const __half* __restrict__ Bh, const __half* __restrict__ Bl,
    int a_rs, int b_rs,
    float* __restrict__ Cf, __half* __restrict__ Ch, int c_ld,
    const float* __restrict__ E, float scale, int K,
    int bm, int bn, int terms, int epi, SmemT& sm)
{
    const int tid  = threadIdx.x;
    const int wid  = tid >> 5;
    const int lane = tid & 31;
    const int g  = lane >> 2;
    const int tg = lane & 3;
    const int wm = (wid >> 2) * 64;
    const int wn = (wid & 3) * 32;

    // ---- staging indices (validated layout, per 16-k sub-stage) ----
    const int ablk = tid >> 5;
    const int amm  = (tid & 31) >> 2;
    const int app  = tid & 3;
    const int aword = ablk * 128 + (tid & 31) * 4;
    const size_t a00 = (size_t)(bm + ablk * 16 + amm) * a_rs + 2 * app;
    const size_t a10 = a00 + (size_t)8 * a_rs;
    const int bnb = tid >> 4;
    const int bnn = (tid & 15) >> 1;
    const int bj  = tid & 1;
    const int bword = bnb * 64 + bnn * 8 + bj * 4;
    const size_t b00 = (size_t)(bn + bnb * 8 + bnn) * b_rs + 4 * bj;

    uint32_t Ra[8];
    uint2 Rbh[4], Rbl[4];

    auto loadR = [&](int c) {
#pragma unroll
        for (int s = 0; s < 2; s++) {
            const size_t k = ((size_t)c << 5) + (s << 4);
            Ra[s * 4 + 0] = *reinterpret_cast<const uint32_t*>(Ah + a00 + k);
            Ra[s * 4 + 1] = *reinterpret_cast<const uint32_t*>(Ah + a10 + k);
            Ra[s * 4 + 2] = *reinterpret_cast<const uint32_t*>(Ah + a00 + k + 8);
            Ra[s * 4 + 3] = *reinterpret_cast<const uint32_t*>(Ah + a10 + k + 8);
            Rbh[s * 2 + 0] = *reinterpret_cast<const uint2*>(Bh + b00 + k);
            Rbh[s * 2 + 1] = *reinterpret_cast<const uint2*>(Bh + b00 + k + 8);
            if (terms == 2) {
                Rbl[s * 2 + 0] = *reinterpret_cast<const uint2*>(Bl + b00 + k);
                Rbl[s * 2 + 1] = *reinterpret_cast<const uint2*>(Bl + b00 + k + 8);
            }
        }
    };
    auto storeR = [&](int buf) {
#pragma unroll
        for (int s = 0; s < 2; s++) {
            const int off = s * 1024;
            *reinterpret_cast<uint4*>(&sm[buf][0][aword + off]) =
                make_uint4(Ra[s*4+0], Ra[s*4+1], Ra[s*4+2], Ra[s*4+3]);
            *reinterpret_cast<uint4*>(&sm[buf][1][bword + off]) =
                make_uint4(Rbh[s*2].x, Rbh[s*2+1].x, Rbh[s*2].y, Rbh[s*2+1].y);
            if (terms == 2)
                *reinterpret_cast<uint4*>(&sm[buf][2][bword + off]) =
                    make_uint4(Rbl[s*2].x, Rbl[s*2+1].x, Rbl[s*2].y, Rbl[s*2+1].y);
        }
    };

    float acc[4][4][4];
#pragma unroll
    for (int mt = 0; mt < 4; mt++)
#pragma unroll
        for (int nt = 0; nt < 4; nt++)
#pragma unroll
            for (int q = 0; q < 4; q++) acc[mt][nt][q] = 0.f;

    const int NCH = K >> 5;

    loadR(0); storeR(0);
    loadR(1);
    __syncthreads();

    for (int c = 0; c < NCH; c++) {
        const int st = c & 1;
        if (c + 1 < NCH) storeR(st ^ 1);
        if (c + 2 < NCH) loadR(c + 2);

#pragma unroll
        for (int s = 0; s < 2; s++) {
            const int off = s * 1024;
            uint32_t bh[4][2];
#pragma unroll
            for (int nt = 0; nt < 4; nt++) {
                const int bbase = (((wn >> 3) + nt) << 6) + lane * 2 + off;
                uint2 h2 = *reinterpret_cast<const uint2*>(&sm[st][1][bbase]);
                bh[nt][0] = h2.x; bh[nt][1] = h2.y;
            }
            uint32_t af[4][4];
#pragma unroll
            for (int mt = 0; mt < 4; mt++) {
                const int abase = (((wm >> 4) + mt) << 7) + lane * 4 + off;
                uint4 h4 = *reinterpret_cast<const uint4*>(&sm[st][0][abase]);
                af[mt][0] = h4.x; af[mt][1] = h4.y; af[mt][2] = h4.z; af[mt][3] = h4.w;
            }
#pragma unroll
            for (int mt = 0; mt < 4; mt++)
#pragma unroll
                for (int nt = 0; nt < 4; nt++)
                    mma_f16(acc[mt][nt], af[mt], bh[nt]);
            if (terms == 2) {
                uint32_t bl[4][2];
#pragma unroll
                for (int nt = 0; nt < 4; nt++) {
                    const int bbase = (((wn >> 3) + nt) << 6) + lane * 2 + off;
                    uint2 l2 = *reinterpret_cast<const uint2*>(&sm[st][2][bbase]);
                    bl[nt][0] = l2.x; bl[nt][1] = l2.y;
                }
#pragma unroll
                for (int mt = 0; mt < 4; mt++)
#pragma unroll
                    for (int nt = 0; nt < 4; nt++)
                        mma_f16(acc[mt][nt], af[mt], bl[nt]);
            }
        }

        if (c + 1 < NCH) __syncthreads();
    }

    // ---- epilogue ----
#pragma unroll
    for (int mt = 0; mt < 4; mt++) {
        const int r0 = bm + wm + mt * 16 + g;
#pragma unroll
        for (int nt = 0; nt < 4; nt++) {
            const int c0 = bn + wn + nt * 8 + 2 * tg;
            float2 v0 = make_float2(acc[mt][nt][0], acc[mt][nt][1]);   // row r0
            float2 v1 = make_float2(acc[mt][nt][2], acc[mt][nt][3]);   // row r0+8
            if (epi == 0 || epi == 2) {
                if (epi == 2) {
                    const float q0 = (1.f - E[c0])     * -10000.f;
                    const float q1 = (1.f - E[c0 + 1]) * -10000.f;
                    v0.x = v0.x * scale + q0;  v0.y = v0.y * scale + q1;
                    v1.x = v1.x * scale + q0;  v1.y = v1.y * scale + q1;
                }
                *reinterpret_cast<float2*>(Cf + (size_t)r0 * c_ld + c0)       = v0;
                *reinterpret_cast<float2*>(Cf + (size_t)(r0 + 8) * c_ld + c0) = v1;
            } else {
                if (epi == 3) {           // +bias[m]
                    v0.x += E[r0];     v0.y += E[r0];
                    v1.x += E[r0 + 8]; v1.y += E[r0 + 8];
                } else {                  // epi == 4: +bias[n]
                    v0.x += E[c0]; v0.y += E[c0 + 1];
                    v1.x += E[c0]; v1.y += E[c0 + 1];
                }
                *reinterpret_cast<__half2*>(Ch + (size_t)r0 * c_ld + c0) =
                    __halves2half2(__float2half_rn(v0.x), __float2half_rn(v0.y));
                *reinterpret_cast<__half2*>(Ch + (size_t)(r0 + 8) * c_ld + c0) =
                    __halves2half2(__float2half_rn(v1.x), __float2half_rn(v1.y));
            }
        }
    }
}

// ---------------------------------------------------------------------------
// Merged projections: 3072 CTAs. [0,1024) Q-proj, [1024,2048) K-proj,
// [2048,3072) V^T-proj. Single tail wave instead of three.
// ---------------------------------------------------------------------------
__global__ __launch_bounds__(256, 2)
void proj_kern(const __half* __restrict__ Xq1, const __half* __restrict__ Xk1,
               const __half* __restrict__ Wqth, const __half* __restrict__ Wqtl,
               const __half* __restrict__ Wkth, const __half* __restrict__ Wktl,
               const __half* __restrict__ Wvt,
               __half* __restrict__ Q1, __half* __restrict__ K1, __half* __restrict__ Vt,
               const float* __restrict__ bq, const float* __restrict__ bk,
               const float* __restrict__ bv)
{
    __shared__ SmemT sm;
    const int seg = blockIdx.x >> 10;
    const int idx = blockIdx.x & 1023;
    if (seg == 0) {
        gemm_body(Xq1, Wqth, Wqtl, HID, HID, nullptr, Q1, HID,
                  bq, 1.f, HID, (idx >> 3) * 128, (idx & 7) * 128, 2, 4, sm);
    } else if (seg == 1) {
        gemm_body(Xk1, Wkth, Wktl, HID, HID, nullptr, K1, HID,
                  bk, 1.f, HID, (idx >> 3) * 128, (idx & 7) * 128, 2, 4, sm);
    } else {
        gemm_body(Wvt, Xk1, nullptr, HID, HID, nullptr, Vt, BATCH * SKV,
                  bv, 1.f, HID, (idx >> 7) * 128, (idx & 127) * 128, 1, 3, sm);
    }
}

// Scores: S[b] = Q @ K^T * scale + mask  (1-term, fp32 out)
__global__ __launch_bounds__(256, 2)
void scores_kern(const __half* __restrict__ Q1, const __half* __restrict__ K1,
                 float* __restrict__ S, const float* __restrict__ mask, float scale)
{
    __shared__ SmemT sm;
    const int bz = blockIdx.z;
    gemm_body(Q1 + (size_t)bz * SQ * HID,
              K1 + (size_t)bz * SKV * HID, nullptr,
              HID, HID,
              S + (size_t)bz * SQ * SKV, nullptr, SKV,
              mask + (size_t)bz * SKV, scale, HID,
              blockIdx.y * 128, blockIdx.x * 128, 1, 2, sm);
}

// PV: out[b] = P @ V  (1-term, fp32 out)
__global__ __launch_bounds__(256, 2)
void pv_kern(const __half* __restrict__ Sp, const __half* __restrict__ Vt,
             float* __restrict__ out)
{
    __shared__ SmemT sm;
    const int bz = blockIdx.z;
    gemm_body(Sp + (size_t)bz * SQ * SKV,
              Vt + (size_t)bz * SKV, nullptr,
              SKV, BATCH * SKV,
              out + (size_t)bz * SQ * HID, nullptr, HID,
              nullptr, 1.f, SKV,
              blockIdx.y * 128, blockIdx.x * 128, 1, 0, sm);
}

// ---------------------------------------------------------------------------
// Pre-pass: fp32 -> fp16 single convert (one float4 per thread)
// ---------------------------------------------------------------------------
__global__ __launch_bounds__(256)
void cvt_kern(const float* __restrict__ X, __half* __restrict__ H, int n4)
{
    int i = blockIdx.x * blockDim.x + threadIdx.x;
    if (i >= n4) return;
    float4 v = reinterpret_cast<const float4*>(X)[i];
    cvt4h(H, (size_t)i * 4, v);
}

// ---------------------------------------------------------------------------
// Pre-pass: weight transpose + split (pair) or convert (single).
// ---------------------------------------------------------------------------
template<bool PAIR>
__global__ __launch_bounds__(256)
void tsplit_kern(const float* __restrict__ W, __half* __restrict__ TH,
                 __half* __restrict__ TL)
{
    __shared__ float t[32][33];
    const int bx = blockIdx.x * 32;   // n
    const int by = blockIdx.y * 32;   // k
    const int x = threadIdx.x & 31;
    const int y = threadIdx.x >> 5;
#pragma unroll
    for (int i = 0; i < 4; i++)
        t[y + 8 * i][x] = W[(size_t)(by + y + 8 * i) * HID + bx + x];
    __syncthreads();
#pragma unroll
    for (int i = 0; i < 4; i++) {
        const int n = bx + y + 8 * i, k = by + x;
        if (PAIR) {
            __half h, l;
            split2h(t[x][y + 8 * i], h, l);
            TH[(size_t)n * HID + k] = h;
            TL[(size_t)n * HID + k] = l;
        } else {
            TH[(size_t)n * HID + k] = __float2half_rn(t[x][y + 8 * i]);
        }
    }
}

// ---------------------------------------------------------------------------
// Row softmax over N=2048; reads fp32 scores, writes fp16 single probs.
// ---------------------------------------------------------------------------
__device__ __forceinline__ float warp_max(float v) {
#pragma unroll
    for (int o = 16; o; o >>= 1) v = fmaxf(v, __shfl_xor_sync(0xFFFFFFFFu, v, o));
    return v;
}
__device__ __forceinline__ float warp_sum(float v) {
#pragma unroll
    for (int o = 16; o; o >>= 1) v += __shfl_xor_sync(0xFFFFFFFFu, v, o);
    return v;
}

__global__ __launch_bounds__(256)
void softmax_kern(const float* __restrict__ S, __half* __restrict__ P)
{
    const size_t row = blockIdx.x;
    const float* p = S + row * (size_t)SKV;
    const int tid = threadIdx.x;

    float4 v0 = *reinterpret_cast<const float4*>(p + tid * 4);
    float4 v1 = *reinterpret_cast<const float4*>(p + 1024 + tid * 4);

    float m = fmaxf(fmaxf(fmaxf(v0.x, v0.y), fmaxf(v0.z, v0.w)),
                    fmaxf(fmaxf(v1.x, v1.y), fmaxf(v1.z, v1.w)));

    __shared__ float red[8];
    float wm = warp_max(m);
    if ((tid & 31) == 0) red[tid >> 5] = wm;
    __syncthreads();
    float bm = red[0];
#pragma unroll
    for (int i = 1; i < 8; i++) bm = fmaxf(bm, red[i]);
    __syncthreads();

    v0.x = expf(v0.x - bm); v0.y = expf(v0.y - bm);
    v0.z = expf(v0.z - bm); v0.w = expf(v0.w - bm);
    v1.x = expf(v1.x - bm); v1.y = expf(v1.y - bm);
    v1.z = expf(v1.z - bm); v1.w = expf(v1.w - bm);

    float s = v0.x + v0.y + v0.z + v0.w + v1.x + v1.y + v1.z + v1.w;
    float ws = warp_sum(s);
    if ((tid & 31) == 0) red[tid >> 5] = ws;
    __syncthreads();
    float bs = 0.f;
#pragma unroll
    for (int i = 0; i < 8; i++) bs += red[i];

    const float inv = 1.f / bs;
    v0.x *= inv; v0.y *= inv; v0.z *= inv; v0.w *= inv;
    v1.x *= inv; v1.y *= inv; v1.z *= inv; v1.w *= inv;

    cvt4h(P, row * (size_t)SKV + tid * 4, v0);
    cvt4h(P, row * (size_t)SKV + 1024 + tid * 4, v1);
}

// ---------------------------------------------------------------------------
// Launch.  Order puts proj_kern at launch index 5 (ncu -s 5 captures it).
// ---------------------------------------------------------------------------
extern "C" void kernel_launch(void* const* d_in, const int* in_sizes, int n_in,
                              void* d_out, int out_size)
{
    const float* Xq   = (const float*)d_in[0];
    const float* Xk   = (const float*)d_in[1];
    const float* mask = (const float*)d_in[2];
    const float* Wq   = (const float*)d_in[3];
    const float* bq   = (const float*)d_in[4];
    const float* Wk   = (const float*)d_in[5];
    const float* bk   = (const float*)d_in[6];
    const float* Wv   = (const float*)d_in[7];
    const float* bv   = (const float*)d_in[8];
    float* out = (float*)d_out;

    __half *Xq1, *Xk1, *Wqth, *Wqtl, *Wkth, *Wktl, *Wvt;
    __half *Q1, *K1, *Vt, *Sp;
    float* S;
    cudaGetSymbolAddress((void**)&Xq1, gXq1);
    cudaGetSymbolAddress((void**)&Xk1, gXk1);
    cudaGetSymbolAddress((void**)&Wqth, gWqth); cudaGetSymbolAddress((void**)&Wqtl, gWqtl);
    cudaGetSymbolAddress((void**)&Wkth, gWkth); cudaGetSymbolAddress((void**)&Wktl, gWktl);
    cudaGetSymbolAddress((void**)&Wvt, gWvt);
    cudaGetSymbolAddress((void**)&Q1, gQ1);
    cudaGetSymbolAddress((void**)&K1, gK1);
    cudaGetSymbolAddress((void**)&Vt, gVt);
    cudaGetSymbolAddress((void**)&S, gS);
    cudaGetSymbolAddress((void**)&Sp, gSp);

    const float scale = 1.f / 32.f;   // 1/sqrt(1024)
    const int n4 = (int)(NX / 4);

    // #0-2: weight prep   #3-4: input converts
    tsplit_kern<true ><<<dim3(32, 32), 256>>>(Wq, Wqth, Wqtl);
    tsplit_kern<true ><<<dim3(32, 32), 256>>>(Wk, Wkth, Wktl);
    tsplit_kern<false><<<dim3(32, 32), 256>>>(Wv, Wvt, nullptr);
    cvt_kern<<<(n4 + 255) / 256, 256>>>(Xq, Xq1, n4);
    cvt_kern<<<(n4 + 255) / 256, 256>>>(Xk, Xk1, n4);

    // #5: merged Q/K/V projections (3072 CTAs, single tail)
    proj_kern<<<3072, 256>>>(Xq1, Xk1, Wqth, Wqtl, Wkth, Wktl, Wvt,
                             Q1, K1, Vt, bq, bk, bv);

    // #6: scores
    scores_kern<<<dim3(SKV / 128, SQ / 128, BATCH), 256>>>(Q1, K1, S, mask, scale);

    // #7: softmax -> fp16 probs
    softmax_kern<<<BATCH * SQ, 256>>>(S, Sp);

    // #8: PV
    pv_kern<<<dim3(HID / 128, SQ / 128, BATCH), 256>>>(Sp, Vt, out);
}